// round 4
// baseline (speedup 1.0000x reference)
#include <cuda_runtime.h>
#include <cstdint>
#include <cstddef>

// out[t,e,o] = sum_r x[t, e*128+r] * W[e,o,r]
// x: [8192, 1024] f32, W: [8, 4096, 128] f32, out: [8192, 8, 4096] f32
//
// mma.sync TF32 (legacy tensor path; tcgen05 is unavailable: harness compiles
// via compute_103 PTX which rejects 'a'-suffix features).
//
// Grid = 16 N-tiles(256) x 8 experts = 128 persistent CTAs (1 wave on 148 SMs).
// Per CTA: W[256x128] tf32-rounded resident in SMEM (128KB, loaded once).
// X streamed per 128-row M-iter in two 64-wide K chunks through a 2x32KB
// double buffer by 2 producer warps (LDG -> cvt.rna.tf32 -> swizzled STS),
// mbarrier-synchronized with 8 compute warps (warp tile 64x64 -> 1.0 LDS/MMA).

#define EXPERTS  8
#define RANK     128
#define OUTF     4096
#define BM       128
#define BN       256
#define NTHREADS 320          // 8 compute warps + 2 producer warps

// SMEM layout (bytes)
#define SM_FULL0   0          // mbar: chunk buf0 full   (count 64)
#define SM_FULL1   8
#define SM_FREE0   16         // mbar: chunk buf0 free   (count 256)
#define SM_FREE1   24
#define SM_X       1024       // 2 x 32768: [128 rows][64 tf32] swizzled
#define SM_W       (1024 + 65536)       // 256 rows x 128 tf32 swizzled = 128KB
#define SMEM_TOTAL (SM_W + 131072)      // 197632

__device__ __forceinline__ uint32_t smem_u32(const void* p) {
    uint32_t a;
    asm("{ .reg .u64 t; cvta.to.shared.u64 t, %1; cvt.u32.u64 %0, t; }" : "=r"(a) : "l"(p));
    return a;
}
__device__ __forceinline__ uint32_t tf32u(float f) {
    uint32_t u;
    asm("cvt.rna.tf32.f32 %0, %1;" : "=r"(u) : "f"(f));
    return u;
}
__device__ __forceinline__ void mbar_init(uint32_t m, uint32_t cnt) {
    asm volatile("mbarrier.init.shared.b64 [%0], %1;" :: "r"(m), "r"(cnt) : "memory");
}
__device__ __forceinline__ void mbar_arrive(uint32_t m) {
    asm volatile("mbarrier.arrive.release.cta.shared::cta.b64 _, [%0];" :: "r"(m) : "memory");
}
__device__ __forceinline__ void mbar_wait(uint32_t m, uint32_t parity) {
    asm volatile(
        "{\n\t.reg .pred P;\n\t"
        "W_%=:\n\t"
        "mbarrier.try_wait.parity.acquire.cta.shared::cta.b64 P, [%0], %1, 0x989680;\n\t"
        "@!P bra W_%=;\n\t}"
        :: "r"(m), "r"(parity) : "memory");
}
__device__ __forceinline__ void mma_tf32(float c[4], const uint32_t a[4], const uint32_t b[2]) {
    asm volatile(
        "mma.sync.aligned.m16n8k8.row.col.f32.tf32.tf32.f32 "
        "{%0,%1,%2,%3}, {%4,%5,%6,%7}, {%8,%9}, {%0,%1,%2,%3};"
        : "+f"(c[0]), "+f"(c[1]), "+f"(c[2]), "+f"(c[3])
        : "r"(a[0]), "r"(a[1]), "r"(a[2]), "r"(a[3]), "r"(b[0]), "r"(b[1]));
}

extern "C" __global__ void __launch_bounds__(NTHREADS, 1)
moelb_ws(const float* __restrict__ x,
         const float* __restrict__ W,
         float* __restrict__ out,
         int iters)
{
    extern __shared__ char smem[];
    const uint32_t sb = smem_u32(smem);
    float* Xs = reinterpret_cast<float*>(smem + SM_X);
    float* Ws = reinterpret_cast<float*>(smem + SM_W);

    const int tid  = threadIdx.x;
    const int wid  = tid >> 5;
    const int lane = tid & 31;
    const int g    = lane >> 2;
    const int tig  = lane & 3;
    const int sk   = g << 2;

    const int nOff = blockIdx.x * BN;
    const int e    = blockIdx.y;

    // ---- Prologue: resident W tile [256 x 128], SW swizzle, tf32-rounded ----
    {
        const float4* w4 = reinterpret_cast<const float4*>(W)
                         + ((size_t)e * OUTF + nOff) * (RANK / 4);
        for (int idx = tid; idx < BN * (RANK / 4); idx += NTHREADS) {
            int row = idx >> 5;             // 0..255
            int q   = idx & 31;             // float4 within 128 floats
            float4 v = w4[idx];
            uint4 t = make_uint4(tf32u(v.x), tf32u(v.y), tf32u(v.z), tf32u(v.w));
            uint32_t byte = (uint32_t)row * 512 + (((uint32_t)q * 16) ^ (((uint32_t)row & 7) << 4));
            *reinterpret_cast<uint4*>(smem + SM_W + byte) = t;
        }
    }
    if (tid == 0) {
        mbar_init(sb + SM_FULL0, 64);
        mbar_init(sb + SM_FULL1, 64);
        mbar_init(sb + SM_FREE0, 256);
        mbar_init(sb + SM_FREE1, 256);
    }
    __syncthreads();

    if (wid < 8) {
        // ===================== compute warps: warp tile 64x64 =====================
        const int mW = (wid >> 2) * 64;     // 0 or 64
        const int nW = (wid & 3) * 64;      // 0,64,128,192
        uint32_t phf[2] = {0, 0};
        float acc[4][8][4];

        for (int it = 0; it < iters; ++it) {
            #pragma unroll
            for (int mt = 0; mt < 4; ++mt)
                #pragma unroll
                for (int nt = 0; nt < 8; ++nt)
                    #pragma unroll
                    for (int i = 0; i < 4; ++i)
                        acc[mt][nt][i] = 0.0f;

            #pragma unroll
            for (int ch = 0; ch < 2; ++ch) {
                const int buf = ch;
                mbar_wait(sb + SM_FULL0 + buf * 8, phf[buf]); phf[buf] ^= 1;
                const float* Xb = Xs + buf * 8192;   // 32KB chunk

                #pragma unroll
                for (int ks = 0; ks < 8; ++ks) {
                    const int k0  = ks * 8;
                    const int o1x = ( k0      ^ sk) + tig;       // X chunk-local col
                    const int o2x = ((k0 + 4) ^ sk) + tig;
                    const int kg  = ch * 64 + k0;                // W global k
                    const int o1w = ( kg      ^ sk) + tig;
                    const int o2w = ((kg + 4) ^ sk) + tig;

                    uint32_t a[4][4];
                    #pragma unroll
                    for (int mt = 0; mt < 4; ++mt) {
                        int r0 = mW + mt * 16 + g;
                        a[mt][0] = __float_as_uint(Xb[(r0    ) * 64 + o1x]);
                        a[mt][1] = __float_as_uint(Xb[(r0 + 8) * 64 + o1x]);
                        a[mt][2] = __float_as_uint(Xb[(r0    ) * 64 + o2x]);
                        a[mt][3] = __float_as_uint(Xb[(r0 + 8) * 64 + o2x]);
                    }
                    uint32_t b[8][2];
                    #pragma unroll
                    for (int nt = 0; nt < 8; ++nt) {
                        int n = nW + nt * 8 + g;
                        b[nt][0] = __float_as_uint(Ws[n * RANK + o1w]);
                        b[nt][1] = __float_as_uint(Ws[n * RANK + o2w]);
                    }
                    #pragma unroll
                    for (int mt = 0; mt < 4; ++mt)
                        #pragma unroll
                        for (int nt = 0; nt < 8; ++nt)
                            mma_tf32(acc[mt][nt], a[mt], b[nt]);
                }
                mbar_arrive(sb + SM_FREE0 + buf * 8);
            }

            // ---- epilogue: out[t, e, o] ----
            #pragma unroll
            for (int mt = 0; mt < 4; ++mt) {
                const int t0 = it * BM + mW + mt * 16 + g;
                float* p0 = out + ((size_t)t0 * EXPERTS + e) * OUTF + nOff + nW;
                float* p1 = p0 + (size_t)8 * EXPERTS * OUTF;
                #pragma unroll
                for (int nt = 0; nt < 8; ++nt) {
                    int o = nt * 8 + 2 * tig;
                    *reinterpret_cast<float2*>(p0 + o) =
                        make_float2(acc[mt][nt][0], acc[mt][nt][1]);
                    *reinterpret_cast<float2*>(p1 + o) =
                        make_float2(acc[mt][nt][2], acc[mt][nt][3]);
                }
            }
        }
    } else {
        // ===================== producer warps (wid 8,9) =====================
        const int pw = wid - 8;             // row half: 0 -> rows 0-63, 1 -> 64-127
        const float4* x4 = reinterpret_cast<const float4*>(x);
        uint32_t phr[2] = {0, 0};
        const int nchunks = iters * 2;

        for (int ci = 0; ci < nchunks; ++ci) {
            const int buf = ci & 1;
            if (ci >= 2) { mbar_wait(sb + SM_FREE0 + buf * 8, phr[buf]); phr[buf] ^= 1; }
            const int i = ci >> 1, c = ci & 1;
            const float4* src = x4 + ((size_t)(i * BM + pw * 64)) * 256 + e * 32 + c * 16;
            char* dst = smem + SM_X + buf * 32768 + pw * (64 * 256);

            #pragma unroll 8
            for (int p = 0; p < 32; ++p) {
                int idx = p * 32 + lane;    // 0..1023
                int r   = idx >> 4;         // local row 0..63
                int q   = idx & 15;         // float4 within 64 floats
                float4 v = src[(size_t)r * 256 + q];
                uint4 t = make_uint4(tf32u(v.x), tf32u(v.y), tf32u(v.z), tf32u(v.w));
                uint32_t byte = (uint32_t)r * 256 + (((uint32_t)q * 16) ^ (((uint32_t)r & 7) << 4));
                *reinterpret_cast<uint4*>(dst + byte) = t;
            }
            mbar_arrive(sb + SM_FULL0 + buf * 8);
        }
    }
    __syncthreads();
}

extern "C" void kernel_launch(void* const* d_in, const int* in_sizes, int n_in,
                              void* d_out, int out_size)
{
    const float* x = (const float*)d_in[0];
    const float* W = (const float*)d_in[1];
    float* out = (float*)d_out;

    const int T = in_sizes[0] / (EXPERTS * RANK);
    const int iters = T / BM;

    cudaFuncSetAttribute(moelb_ws,
                         cudaFuncAttributeMaxDynamicSharedMemorySize, SMEM_TOTAL);

    dim3 grid(OUTF / BN, EXPERTS);
    moelb_ws<<<grid, NTHREADS, SMEM_TOTAL>>>(x, W, out, iters);
}